// round 3
// baseline (speedup 1.0000x reference)
#include <cuda_runtime.h>
#include <cstdint>

#define B_   64
#define T_   512
#define H_   512
#define E_   128
#define C_   1000
#define G7   (7 * H_)    // 3584
#define OUTW (6 * H_)    // 3072
#define NCTA 128
#define NTHR 256

typedef unsigned long long ull;

// ---- device-global scratch ----
__device__ float g_tg[C_ * G7];        // table_gates = emb @ W1 + b   (14.3 MB)
__device__ float g_h[2][H_][B_];       // h_d double buffer, [buf][k][b]
__device__ int           g_count;
__device__ volatile int  g_sense;

// ---- helpers ----
__device__ __forceinline__ float sigf(float x)      { return 1.0f / (1.0f + expf(-x)); }
__device__ __forceinline__ float softplusf(float x) { return fmaxf(x, 0.0f) + log1pf(expf(-fabsf(x))); }

__device__ __forceinline__ void ffma2(ull& d, ull a, ull b)
{
    asm("fma.rn.f32x2 %0, %1, %2, %0;" : "+l"(d) : "l"(a), "l"(b));
}

__device__ __forceinline__ void grid_sync(int* sense)
{
    __threadfence();
    __syncthreads();
    if (threadIdx.x == 0) {
        int s = *sense ^ 1;
        *sense = s;
        if (atomicAdd(&g_count, 1) == (int)gridDim.x - 1) {
            g_count = 0;
            __threadfence();
            g_sense = s;
        } else {
            while (g_sense != s) { __nanosleep(64); }
            __threadfence();
        }
    }
    __syncthreads();
}

// =====================  Kernel 1: table_gates  =====================
__global__ void tg_kernel(const float* __restrict__ emb,
                          const float* __restrict__ W,
                          const float* __restrict__ bias)
{
    __shared__ float sh_e[16][E_];
    const int col = blockIdx.x * 256 + threadIdx.x;
    const int c0  = blockIdx.y * 16;

    for (int i = threadIdx.x; i < 16 * E_; i += 256) {
        int ci = i >> 7, e = i & 127;
        int c  = c0 + ci;
        sh_e[ci][e] = (c < C_) ? emb[c * E_ + e] : 0.0f;
    }
    __syncthreads();

    float acc[16];
#pragma unroll
    for (int i = 0; i < 16; ++i) acc[i] = 0.0f;

    for (int e = 0; e < E_; ++e) {
        float wv = W[e * G7 + col];
#pragma unroll
        for (int i = 0; i < 16; ++i) acc[i] = fmaf(sh_e[i][e], wv, acc[i]);
    }
    float bb = bias[col];
#pragma unroll
    for (int i = 0; i < 16; ++i) {
        int c = c0 + i;
        if (c < C_) g_tg[c * G7 + col] = acc[i] + bb;
    }
}

// =====================  Kernel 2: persistent recurrence  =====================
// 128 CTAs x 256 threads. CTA owns j in [4*cta, 4*cta+4) (28 gate cols).
// tid = ks*64 + r ; ks in 0..3 (K quarter / batch slot), r = bg*4 + jl.
#define W2_F    (512 * 28 * 2)       // 28672 floats (duplicated-pair weights)
#define HBUF_F  (128 * 64)           //  8192 floats per h chunk buffer
#define RSTRIDE 30
#define RED_F   (4 * 64 * RSTRIDE)   //  7680 floats
#define SMEM_F  (W2_F + 2 * HBUF_F + RED_F)
#define SMEM_BYTES (SMEM_F * 4)      // 210944 B

__global__ void __launch_bounds__(NTHR, 1)
rec_kernel(const int*   __restrict__ marks,
           const float* __restrict__ ts,
           const float* __restrict__ Wc,
           const float* __restrict__ init,
           float*       __restrict__ out)
{
    extern __shared__ float smem[];
    float* sh_W   = smem;
    float* sh_hA  = smem + W2_F;
    float* sh_hB  = sh_hA + HBUF_F;
    float* sh_red = sh_hB + HBUF_F;

    const int tid = threadIdx.x;
    const int cta = blockIdx.x;
    const int ks  = tid >> 6;
    const int r   = tid & 63;
    const int bg  = r >> 2;
    const int jl  = r & 3;
    const int j   = cta * 4 + jl;
    const int b   = bg * 4 + ks;     // this thread's batch element (epilogue)

    // ---- load resident W slice, duplicated into float2 (w,w) ----
    {
        float2* Wp = (float2*)sh_W;
        for (int idx = tid; idx < 512 * 28; idx += NTHR) {
            int k   = idx / 28;
            int c28 = idx - k * 28;
            int g   = c28 >> 2, jj = c28 & 3;
            float w = Wc[(size_t)(E_ + k) * G7 + g * H_ + cta * 4 + jj];
            Wp[idx] = make_float2(w, w);
        }
    }

    // ---- init h buffer ----
    for (int idx = tid; idx < 4 * 64; idx += NTHR) {
        int jj = idx >> 6, bb = idx & 63;
        g_h[0][cta * 4 + jj][bb] = tanhf(init[cta * 4 + jj]);
    }

    // ---- output row t=0 ----
    for (int idx = tid; idx < 4 * 6 * 64; idx += NTHR) {
        int bb = idx & 63; int rest = idx >> 6;
        int f = rest % 6; int jj = rest / 6;
        int jg = cta * 4 + jj;
        float v;
        switch (f) {
            case 0:  v = tanhf(init[0 * H_ + jg]);     break;
            case 1:  v = sigf (init[5 * H_ + jg]);     break;
            case 2:  v = tanhf(init[2 * H_ + jg]);     break;
            case 3:  v = tanhf(init[3 * H_ + jg]);     break;
            case 4:  v = softplusf(init[4 * H_ + jg]); break;
            default: v = tanhf(init[1 * H_ + jg]);     break;
        }
        out[(size_t)bb * (513 * OUTW) + f * H_ + jg] = v;
    }

    // ---- per-(b,j) recurrent state ----
    float c_d = tanhf(init[H_ + j]);
    float c_b = tanhf(init[2 * H_ + j]);

    int sense = 0;
    grid_sync(&sense);   // 1 + 511 = 512 flips per launch (even -> replay safe)

    for (int t = 0; t < T_; ++t) {
        const float* hcur = &g_h[t & 1][0][0];

        // ---- epilogue prefetch: issue long-latency loads BEFORE the matmul ----
        int   m    = __ldg(&marks[b * T_ + t]);
        float tsv  = __ldg(&ts[b * T_ + t]);
        float tsp  = (t > 0) ? __ldg(&ts[b * T_ + t - 1]) : 0.0f;
        const float* tgp = g_tg + (size_t)m * G7 + j;
        float tg0 = __ldcg(tgp + 0 * H_);
        float tg1 = __ldcg(tgp + 1 * H_);
        float tg2 = __ldcg(tgp + 2 * H_);
        float tg3 = __ldcg(tgp + 3 * H_);
        float tg4 = __ldcg(tgp + 4 * H_);
        float tg5 = __ldcg(tgp + 5 * H_);
        float tg6 = __ldcg(tgp + 6 * H_);

        ull acc[14];
#pragma unroll
        for (int i = 0; i < 14; ++i) acc[i] = 0ull;

        // ---- prologue: stage chunk 0 ----
        float4 pre[8];
#pragma unroll
        for (int i = 0; i < 8; ++i) {
            int L = i * NTHR + tid;
            int b4 = (L & 15) << 2, kl = L >> 4;
            pre[i] = __ldcg((const float4*)(hcur + kl * 64 + b4));
        }
#pragma unroll
        for (int i = 0; i < 8; ++i) {
            int L = i * NTHR + tid;
            int b4 = (L & 15) << 2, kl = L >> 4;
            *(float4*)(sh_hA + kl * 64 + b4) = pre[i];
        }
        __syncthreads();

        float* bufs[2] = { sh_hA, sh_hB };
        for (int c = 0; c < 4; ++c) {
            if (c < 3) {   // prefetch next chunk
#pragma unroll
                for (int i = 0; i < 8; ++i) {
                    int L = i * NTHR + tid;
                    int b4 = (L & 15) << 2, kl = L >> 4;
                    pre[i] = __ldcg((const float4*)(hcur + ((c + 1) * 128 + kl) * 64 + b4));
                }
            }

            const ull* hp = (const ull*)bufs[c & 1] + (ks * 32) * 32 + bg * 2;
            const ull* wp = (const ull*)sh_W + (c * 128 + ks * 32) * 28 + jl;
#pragma unroll 8
            for (int kk = 0; kk < 32; ++kk) {
                ull h0 = hp[0], h1 = hp[1]; hp += 32;
#pragma unroll
                for (int g = 0; g < 7; ++g) {
                    ull w = wp[g * 4];
                    ffma2(acc[g * 2],     w, h0);
                    ffma2(acc[g * 2 + 1], w, h1);
                }
                wp += 28;
            }

            if (c < 3) {
                float* nb = bufs[(c + 1) & 1];
#pragma unroll
                for (int i = 0; i < 8; ++i) {
                    int L = i * NTHR + tid;
                    int b4 = (L & 15) << 2, kl = L >> 4;
                    *(float4*)(nb + kl * 64 + b4) = pre[i];
                }
                __syncthreads();
            }
        }

        // ---- cross-ks reduction ----
        {
            ull* rb = (ull*)(sh_red + (ks * 64 + r) * RSTRIDE);
#pragma unroll
            for (int i = 0; i < 14; ++i) rb[i] = acc[i];
        }
        __syncthreads();

        float a[7];
#pragma unroll
        for (int g = 0; g < 7; ++g) a[g] = 0.0f;
#pragma unroll
        for (int s = 0; s < 4; ++s) {
            const float* rp = sh_red + (s * 64 + r) * RSTRIDE;
#pragma unroll
            for (int g = 0; g < 7; ++g) a[g] += rp[g * 4 + ks];
        }

        // ---- epilogue: one (b, j) per thread ----
        {
            float dur = tsv - tsp;

            float gi  = sigf (a[0] + tg0);
            float gf  = sigf (a[1] + tg1);
            float gz  = tanhf(a[2] + tg2);
            float go  = sigf (a[3] + tg3);
            float gib = sigf (a[4] + tg4);
            float gfb = sigf (a[5] + tg5);
            float gd  = softplusf(a[6] + tg6);

            float c  = gf * c_d + gi * gz;
            float cb = gfb * c_b + gib * gz;
            float cd = cb + (c - cb) * expf(-gd * dur);
            float hd = go * tanhf(cd);
            c_d = cd; c_b = cb;

            size_t ob = (size_t)b * (513 * OUTW) + (size_t)(t + 1) * OUTW + j;
            out[ob]          = hd;
            out[ob + 1 * H_] = go;
            out[ob + 2 * H_] = cb;
            out[ob + 3 * H_] = c;
            out[ob + 4 * H_] = gd;
            out[ob + 5 * H_] = cd;

            g_h[(t + 1) & 1][j][b] = hd;
        }

        if (t != T_ - 1) grid_sync(&sense);
    }
}

// =====================  launch  =====================
extern "C" void kernel_launch(void* const* d_in, const int* in_sizes, int n_in,
                              void* d_out, int out_size)
{
    const int*   marks = (const int*)  d_in[0];
    const float* ts    = (const float*)d_in[1];
    const float* emb   = (const float*)d_in[2];
    const float* Wc    = (const float*)d_in[3];
    const float* bc    = (const float*)d_in[4];
    const float* init  = (const float*)d_in[5];
    float*       out   = (float*)d_out;

    dim3 g1(G7 / 256, (C_ + 15) / 16);
    tg_kernel<<<g1, 256>>>(emb, Wc, bc);

    cudaFuncSetAttribute(rec_kernel, cudaFuncAttributeMaxDynamicSharedMemorySize, SMEM_BYTES);
    rec_kernel<<<NCTA, NTHR, SMEM_BYTES>>>(marks, ts, Wc, init, out);
}